// round 9
// baseline (speedup 1.0000x reference)
#include <cuda_runtime.h>
#include <math_constants.h>

// feature_matrix_batch: [S=2, N=32, I=4096, D=128] f32
// cluster_index:        [S, N*I] int32 or int64, values in [n*K,(n+1)*K)
// output:               [S, N, K=16, D=128] f32 segment max (-inf identity)

#define SS      2
#define NN      32
#define II      4096
#define DD      128
#define KK      16
#define CHUNKS  16
#define PTS     (II / CHUNKS)        // 256 points per block
#define NBLK    (SS * NN * CHUNKS)   // 1024 blocks (~6.9/SM, balanced)
#define ROWF4   32                   // float4 per row (128 floats)
#define TILE    (KK * ROWF4)         // 512 float4 per block partial
#define WPTS    (PTS / 4)            // 64 points per warp
#define NGRP    (WPTS / 4)           // 16 groups of 4 points

// Per-block partials: [1024][512 f4] = 8 MB, plus per-cloud arrival counters.
__device__ float4 g_scratch4[NBLK * TILE];
__device__ int    g_count[SS * NN];   // zero-init; reset by reducer each run

__global__ void __launch_bounds__(128) maxpool_fused(
    const float4* __restrict__ f4,
    const int*    __restrict__ cw,     // raw 32-bit view of cluster_index
    float4*       __restrict__ out4)
{
    const int b     = blockIdx.x;
    const int chunk = b & (CHUNKS - 1);
    const int cloud = b >> 4;                 // CHUNKS == 16
    const int n     = cloud & (NN - 1);
    const int x     = threadIdx.x;
    const int w     = x >> 5;
    const int lane  = x & 31;

    __shared__ float4 smaxw[4][KK + 1][ROWF4];  // 34 KB (row 16 = trash row)
    __shared__ int    soff[PTS];                // 1 KB
    __shared__ int    s_last;

    // dtype sniff: indices < 512 -> int64 high (odd) words all zero.
    const bool is64 =
        ((cw[1] | cw[3] | cw[5] | cw[7] | cw[9] | cw[11] | cw[13] | cw[15]) == 0);

    const float4 neg4 = make_float4(-CUDART_INF_F, -CUDART_INF_F,
                                    -CUDART_INF_F, -CUDART_INF_F);
    #pragma unroll
    for (int r = 0; r <= KK; r++)
        smaxw[w][r][lane] = neg4;

    // Stage indices -> clamped local segment id (branch-free consumer).
    const size_t idx_base = (size_t)cloud * II + (size_t)chunk * PTS;
    if (is64) {
        #pragma unroll
        for (int j = x; j < PTS; j += 128) {
            int k = cw[2 * (idx_base + j)] - n * KK;   // low word of int64
            soff[j] = (int)min((unsigned)k, (unsigned)KK);
        }
    } else {
        #pragma unroll
        for (int j = x; j < PTS; j += 128) {
            int k = cw[idx_base + j] - n * KK;
            soff[j] = (int)min((unsigned)k, (unsigned)KK);
        }
    }
    __syncthreads();

    // Warp w owns contiguous points [w*64, (w+1)*64) of this chunk.
    const int     pbase = w * WPTS;
    const float4* fp    = f4 + ((size_t)cloud * II + (size_t)chunk * PTS
                                + pbase) * ROWF4 + lane;
    float4* const my    = &smaxw[w][0][lane];   // row stride = ROWF4 float4

    // ---- depth-2 double-buffered pipeline: 8 LDG.128 (4 KB) in flight ----
    float4 vb[2][4];
    int    kb[2][4];
    #pragma unroll
    for (int u = 0; u < 4; u++) {               // group 0
        vb[0][u] = fp[(0 * 4 + u) * ROWF4];
        kb[0][u] = soff[pbase + 0 * 4 + u];
    }
    #pragma unroll
    for (int u = 0; u < 4; u++) {               // group 1
        vb[1][u] = fp[(1 * 4 + u) * ROWF4];
        kb[1][u] = soff[pbase + 1 * 4 + u];
    }

    #pragma unroll
    for (int g = 0; g < NGRP; g++) {
        const int s = g & 1;
        // consume group g
        #pragma unroll
        for (int u = 0; u < 4; u++) {
            const int   k = kb[s][u];
            const float4 v = vb[s][u];
            float4 c = my[k * ROWF4];
            c.x = fmaxf(c.x, v.x);
            c.y = fmaxf(c.y, v.y);
            c.z = fmaxf(c.z, v.z);
            c.w = fmaxf(c.w, v.w);
            my[k * ROWF4] = c;
        }
        // refill this buffer with group g+2
        if (g + 2 < NGRP) {
            #pragma unroll
            for (int u = 0; u < 4; u++) {
                vb[s][u] = fp[((g + 2) * 4 + u) * ROWF4];
                kb[s][u] = soff[pbase + (g + 2) * 4 + u];
            }
        }
    }
    __syncthreads();

    // ---- merge 4 warp-copies, write block partial ----
    float4* dst = g_scratch4 + (size_t)b * TILE;
    #pragma unroll
    for (int q = 0; q < 4; q++) {
        const int idx = x + 128 * q;           // 0..511
        const int r = idx >> 5, l = idx & 31;
        float4 a = smaxw[0][r][l];
        const float4 b1 = smaxw[1][r][l];
        const float4 b2 = smaxw[2][r][l];
        const float4 b3 = smaxw[3][r][l];
        a.x = fmaxf(fmaxf(a.x, b1.x), fmaxf(b2.x, b3.x));
        a.y = fmaxf(fmaxf(a.y, b1.y), fmaxf(b2.y, b3.y));
        a.z = fmaxf(fmaxf(a.z, b1.z), fmaxf(b2.z, b3.z));
        a.w = fmaxf(fmaxf(a.w, b1.w), fmaxf(b2.w, b3.w));
        dst[idx] = a;
    }

    // ---- last block of each cloud reduces its 16 partials to out ----
    __threadfence();
    __syncthreads();
    if (x == 0)
        s_last = (atomicAdd(&g_count[cloud], 1) == CHUNKS - 1);
    __syncthreads();

    if (s_last) {
        __threadfence();   // acquire-side: order partial reads after counter
        const float4* base = g_scratch4 + (size_t)cloud * CHUNKS * TILE;
        float4*       dout = out4 + (size_t)cloud * TILE;
        #pragma unroll
        for (int q = 0; q < 4; q++) {
            const int idx = x + 128 * q;
            float4 m = base[idx];
            #pragma unroll
            for (int c = 1; c < CHUNKS; c++) {
                const float4 t = base[(size_t)c * TILE + idx];
                m.x = fmaxf(m.x, t.x);
                m.y = fmaxf(m.y, t.y);
                m.z = fmaxf(m.z, t.z);
                m.w = fmaxf(m.w, t.w);
            }
            dout[idx] = m;
        }
        if (x == 0) g_count[cloud] = 0;   // rearm for next graph replay
    }
}

extern "C" void kernel_launch(void* const* d_in, const int* in_sizes, int n_in,
                              void* d_out, int out_size)
{
    const float4* f4  = (const float4*)d_in[0];
    const int*    cw  = (const int*)d_in[1];
    float4*       out = (float4*)d_out;

    maxpool_fused<<<NBLK, 128>>>(f4, cw, out);
}

// round 10
// speedup vs baseline: 1.1396x; 1.1396x over previous
#include <cuda_runtime.h>
#include <math_constants.h>

// feature_matrix_batch: [S=2, N=32, I=4096, D=128] f32
// cluster_index:        [S, N*I] int32 or int64, values in [n*K,(n+1)*K)
// output:               [S, N, K=16, D=128] f32 segment max (-inf identity)

#define SS      2
#define NN      32
#define II      4096
#define DD      128
#define KK      16
#define CHUNKS  8
#define PTS     (II / CHUNKS)        // 512 points per block
#define NBLK    (SS * NN * CHUNKS)   // 512 blocks
#define ROWF4   32                   // float4 per row (128 floats)
#define TILE    (KK * ROWF4)         // 512 float4 per block partial
#define WPTS    (PTS / 4)            // 128 points per warp
#define GRP     4                    // points per group
#define NGRP    (WPTS / GRP)         // 32 groups per warp
#define DEPTH   4                    // pipeline depth: 16 LDG.128 in flight

// Per-block partials: [512][512 f4] = 4 MB, plus per-cloud arrival counters.
__device__ float4 g_scratch4[NBLK * TILE];
__device__ int    g_count[SS * NN];   // zero-init; reset by reducer each run

__global__ void __launch_bounds__(128) maxpool_fused(
    const float4* __restrict__ f4,
    const int*    __restrict__ cw,     // raw 32-bit view of cluster_index
    float4*       __restrict__ out4)
{
    const int b     = blockIdx.x;
    const int chunk = b & (CHUNKS - 1);
    const int cloud = b >> 3;                 // CHUNKS == 8
    const int n     = cloud & (NN - 1);
    const int x     = threadIdx.x;
    const int w     = x >> 5;
    const int lane  = x & 31;

    __shared__ float4 smaxw[4][KK + 1][ROWF4];  // 34 KB (row 16 = trash row)
    __shared__ int    soff[PTS];                // 2 KB
    __shared__ int    s_last;

    // dtype sniff: indices < 512 -> int64 high (odd) words all zero.
    const bool is64 =
        ((cw[1] | cw[3] | cw[5] | cw[7] | cw[9] | cw[11] | cw[13] | cw[15]) == 0);

    const float4 neg4 = make_float4(-CUDART_INF_F, -CUDART_INF_F,
                                    -CUDART_INF_F, -CUDART_INF_F);
    #pragma unroll
    for (int r = 0; r <= KK; r++)
        smaxw[w][r][lane] = neg4;

    // Stage indices -> clamped local segment id (branch-free consumer).
    const size_t idx_base = (size_t)cloud * II + (size_t)chunk * PTS;
    if (is64) {
        #pragma unroll
        for (int j = x; j < PTS; j += 128) {
            int k = cw[2 * (idx_base + j)] - n * KK;   // low word of int64
            soff[j] = (int)min((unsigned)k, (unsigned)KK);
        }
    } else {
        #pragma unroll
        for (int j = x; j < PTS; j += 128) {
            int k = cw[idx_base + j] - n * KK;
            soff[j] = (int)min((unsigned)k, (unsigned)KK);
        }
    }
    __syncthreads();

    // Warp w owns contiguous points [w*128, (w+1)*128) of this chunk.
    const int     pbase = w * WPTS;
    const float4* fp    = f4 + ((size_t)cloud * II + (size_t)chunk * PTS
                                + pbase) * ROWF4 + lane;
    float4* const my    = &smaxw[w][0][lane];   // row stride = ROWF4 float4

    // ---- depth-4 pipeline: 16 LDG.128 (8 KB) in flight per warp ----
    float4 vb[DEPTH][GRP];
    int    kb[DEPTH][GRP];
    #pragma unroll
    for (int d = 0; d < DEPTH; d++)
        #pragma unroll
        for (int u = 0; u < GRP; u++) {
            vb[d][u] = fp[(d * GRP + u) * ROWF4];
            kb[d][u] = soff[pbase + d * GRP + u];
        }

    #pragma unroll
    for (int g = 0; g < NGRP; g++) {
        const int s = g & (DEPTH - 1);
        // consume group g
        #pragma unroll
        for (int u = 0; u < GRP; u++) {
            const int    k = kb[s][u];
            const float4 v = vb[s][u];
            float4 c = my[k * ROWF4];
            c.x = fmaxf(c.x, v.x);
            c.y = fmaxf(c.y, v.y);
            c.z = fmaxf(c.z, v.z);
            c.w = fmaxf(c.w, v.w);
            my[k * ROWF4] = c;
        }
        // refill this buffer with group g+DEPTH
        if (g + DEPTH < NGRP) {
            #pragma unroll
            for (int u = 0; u < GRP; u++) {
                vb[s][u] = fp[((g + DEPTH) * GRP + u) * ROWF4];
                kb[s][u] = soff[pbase + (g + DEPTH) * GRP + u];
            }
        }
    }
    __syncthreads();

    // ---- merge 4 warp-copies, write block partial ----
    float4* dst = g_scratch4 + (size_t)b * TILE;
    #pragma unroll
    for (int q = 0; q < 4; q++) {
        const int idx = x + 128 * q;           // 0..511
        const int r = idx >> 5, l = idx & 31;
        float4 a = smaxw[0][r][l];
        const float4 b1 = smaxw[1][r][l];
        const float4 b2 = smaxw[2][r][l];
        const float4 b3 = smaxw[3][r][l];
        a.x = fmaxf(fmaxf(a.x, b1.x), fmaxf(b2.x, b3.x));
        a.y = fmaxf(fmaxf(a.y, b1.y), fmaxf(b2.y, b3.y));
        a.z = fmaxf(fmaxf(a.z, b1.z), fmaxf(b2.z, b3.z));
        a.w = fmaxf(fmaxf(a.w, b1.w), fmaxf(b2.w, b3.w));
        dst[idx] = a;
    }

    // ---- last block of each cloud reduces its 8 partials to out ----
    __threadfence();
    __syncthreads();
    if (x == 0)
        s_last = (atomicAdd(&g_count[cloud], 1) == CHUNKS - 1);
    __syncthreads();

    if (s_last) {
        __threadfence();   // acquire-side: order partial reads after counter
        const float4* base = g_scratch4 + (size_t)cloud * CHUNKS * TILE;
        float4*       dout = out4 + (size_t)cloud * TILE;
        #pragma unroll
        for (int q = 0; q < 4; q++) {
            const int idx = x + 128 * q;
            float4 m = base[idx];
            #pragma unroll
            for (int c = 1; c < CHUNKS; c++) {
                const float4 t = base[(size_t)c * TILE + idx];
                m.x = fmaxf(m.x, t.x);
                m.y = fmaxf(m.y, t.y);
                m.z = fmaxf(m.z, t.z);
                m.w = fmaxf(m.w, t.w);
            }
            dout[idx] = m;
        }
        if (x == 0) g_count[cloud] = 0;   // rearm for next graph replay
    }
}

extern "C" void kernel_launch(void* const* d_in, const int* in_sizes, int n_in,
                              void* d_out, int out_size)
{
    const float4* f4  = (const float4*)d_in[0];
    const int*    cw  = (const int*)d_in[1];
    float4*       out = (float4*)d_out;

    maxpool_fused<<<NBLK, 128>>>(f4, cw, out);
}